// round 4
// baseline (speedup 1.0000x reference)
#include <cuda_runtime.h>
#include <cstdint>

#define SIZE 8192
#define NB 64
#define BS 128

// Scratch: intermediate in permuted plane layout A2[k2][c2][b] (64*128*4096 floats)
__device__ float g_h[33554432];

__device__ __forceinline__ uint32_t f2tf(float f) {
    uint32_t r;
    asm("cvt.rna.tf32.f32 %0, %1;" : "=r"(r) : "f"(f));
    return r;
}

__device__ __forceinline__ void mma8(float* d, const uint32_t* a, const uint32_t* b) {
    asm volatile(
        "mma.sync.aligned.m16n8k8.row.col.f32.tf32.tf32.f32 "
        "{%0,%1,%2,%3},{%4,%5,%6,%7},{%8,%9},{%0,%1,%2,%3};"
        : "+f"(d[0]), "+f"(d[1]), "+f"(d[2]), "+f"(d[3])
        : "r"(a[0]), "r"(a[1]), "r"(a[2]), "r"(a[3]), "r"(b[0]), "r"(b[1]));
}

// Pads (in words) chosen for conflict-free fragment LDS:
//  pass1 A  [m][k]  pad 132 (132%32==4  -> banks 4g+tg distinct)
//  pass1 B  [k][n]  pad 72  (72%32==8   -> banks 8tg+g distinct)
//  pass1 DT [d][b]  pad 132 (store banks 8tg+g distinct)
//  pass2 AT [c2][b] pad 136 (136%32==8  -> banks 8tg+g distinct)
//  pass2 B  [k][n]  pad 136
#define PA1 132
#define PB1 72
#define PDT 132
#define PA2 136
#define PB2 136

#define SMEM1 ((128 * PA1 + 128 * PB1) * 4)
#define SMEM2 ((128 * PA2 + 128 * PB2) * 4)

// ---------------- pass 1: per-block GEMM x @ w1, epilogue writes permuted planes ----------------
// CTA: kblk (x>>1), nh (x&1): computes D[b0:+128][d = nh*64 : +64] for block kblk,
// then scatters D into A2[dg>>1][kblk + 64*(dg&1)][b] with an smem transpose (coalesced 512B runs).
__global__ void __launch_bounds__(256, 2) monarch_pass1(const float* __restrict__ X,
                                                        const float* __restrict__ W1, int B) {
    extern __shared__ float sm[];
    float* As = sm;               // [128][PA1]  x tile (m,k)
    float* Bs = sm + 128 * PA1;   // [128][PB1]  w1 slice (k,n=64)

    int t = threadIdx.x, lane = t & 31, w = t >> 5;
    int kblk = blockIdx.x >> 1, nh = blockIdx.x & 1;
    int b0 = blockIdx.y * 128;

    // stage A: x[b0:+128][kblk*128:+128], rna-rounded to tf32
    const float* xp = X + (size_t)b0 * SIZE + kblk * BS;
#pragma unroll
    for (int i = 0; i < 16; i++) {
        int r = i * 8 + w;
        float4 v = make_float4(0.f, 0.f, 0.f, 0.f);
        if (b0 + r < B) v = *(const float4*)(xp + (size_t)r * SIZE + lane * 4);
        uint4 u = make_uint4(f2tf(v.x), f2tf(v.y), f2tf(v.z), f2tf(v.w));
        *(uint4*)&As[r * PA1 + lane * 4] = u;
    }
    // stage B: w1[kblk][0:128][nh*64:+64]
    const float* wp = W1 + kblk * BS * BS + nh * 64;
#pragma unroll
    for (int i = 0; i < 8; i++) {
        int k = i * 16 + (t >> 4);
        float4 v = *(const float4*)(wp + k * BS + (t & 15) * 4);
        uint4 u = make_uint4(f2tf(v.x), f2tf(v.y), f2tf(v.z), f2tf(v.w));
        *(uint4*)&Bs[k * PB1 + (t & 15) * 4] = u;
    }
    __syncthreads();

    int wm = w >> 1, wn = w & 1, g = lane >> 2, tg = lane & 3;
    int m0 = wm * 32, n0 = wn * 32;

    float d[2][4][4];
#pragma unroll
    for (int mi = 0; mi < 2; mi++)
#pragma unroll
        for (int s = 0; s < 4; s++)
#pragma unroll
            for (int j = 0; j < 4; j++) d[mi][s][j] = 0.f;

#pragma unroll
    for (int kk = 0; kk < 16; kk++) {
        int k0 = kk * 8;
        uint32_t a[2][4], b[4][2];
#pragma unroll
        for (int mi = 0; mi < 2; mi++) {
            const float* ap = &As[(m0 + mi * 16 + g) * PA1 + k0 + tg];
            a[mi][0] = __float_as_uint(ap[0]);
            a[mi][1] = __float_as_uint(ap[8 * PA1]);
            a[mi][2] = __float_as_uint(ap[4]);
            a[mi][3] = __float_as_uint(ap[8 * PA1 + 4]);
        }
#pragma unroll
        for (int s = 0; s < 4; s++) {
            const float* bp = &Bs[(k0 + tg) * PB1 + n0 + s * 8 + g];
            b[s][0] = __float_as_uint(bp[0]);
            b[s][1] = __float_as_uint(bp[4 * PB1]);
        }
#pragma unroll
        for (int mi = 0; mi < 2; mi++)
#pragma unroll
            for (int s = 0; s < 4; s++) mma8(d[mi][s], a[mi], b[s]);
    }

    // transpose D in smem: DT[dl][b], dl = local d (0..63)
    __syncthreads();
    float* DT = sm;  // 64*PDT floats, reuses As
#pragma unroll
    for (int mi = 0; mi < 2; mi++)
#pragma unroll
        for (int s = 0; s < 4; s++) {
            int br = m0 + mi * 16 + g;
            int c0 = n0 + s * 8 + 2 * tg;
            DT[c0 * PDT + br] = d[mi][s][0];
            DT[(c0 + 1) * PDT + br] = d[mi][s][1];
            DT[c0 * PDT + br + 8] = d[mi][s][2];
            DT[(c0 + 1) * PDT + br + 8] = d[mi][s][3];
        }
    __syncthreads();

    // write permuted planes: dg = nh*64+dl -> A2[dg>>1][kblk + 64*(dg&1)][b0..]
    bool okc = (b0 + lane * 4) < B;
#pragma unroll
    for (int i = 0; i < 8; i++) {
        int dl = i * 8 + w;
        int dg = nh * 64 + dl;
        size_t off = ((size_t)(dg >> 1) * BS + (kblk + 64 * (dg & 1))) * (size_t)B + b0 + lane * 4;
        if (okc) *(float4*)(g_h + off) = *(float4*)&DT[dl * PDT + lane * 4];
    }
}

// ---------------- pass 2: per-k2 GEMM A2[k2] @ w2[k2], paired epilogue + bias ----------------
// CTA: k2, mt. A operand staged as AT[c2][b] (already that layout in gmem -> coalesced).
// Warp tile: M32 x N{[wn*32,+32) U [wn*32+64,+32)} so (j, j+64) pairs live in one lane -> float2 out.
__global__ void __launch_bounds__(256, 1) monarch_pass2(const float* __restrict__ W2,
                                                        const float* __restrict__ bias,
                                                        float* __restrict__ OUT, int B) {
    extern __shared__ float sm[];
    float* As = sm;               // [128][PA2]  AT (c2, b)
    float* Bs = sm + 128 * PA2;   // [128][PB2]  w2[k2] (c2, c2')
    __shared__ float2 bsh[64];

    int t = threadIdx.x, lane = t & 31, w = t >> 5;
    int k2 = blockIdx.x, b0 = blockIdx.y * 128;

    if (t < 64) bsh[t] = *(const float2*)(bias + t * BS + 2 * k2);

    // stage A: plane k2, rows c2 = 0..127, cols b0..b0+127 (coalesced 512B rows)
    const float* ap = g_h + (size_t)k2 * BS * (size_t)B + b0;
    bool okc = (b0 + lane * 4) < B;
#pragma unroll
    for (int i = 0; i < 16; i++) {
        int c2 = i * 8 + w;
        float4 v = make_float4(0.f, 0.f, 0.f, 0.f);
        if (okc) v = *(const float4*)(ap + (size_t)c2 * B + lane * 4);
        uint4 u = make_uint4(f2tf(v.x), f2tf(v.y), f2tf(v.z), f2tf(v.w));
        *(uint4*)&As[c2 * PA2 + lane * 4] = u;
    }
    // stage B: w2[k2][0:128][0:128]
    const float* wp = W2 + k2 * BS * BS;
#pragma unroll
    for (int i = 0; i < 16; i++) {
        int k = i * 8 + w;
        float4 v = *(const float4*)(wp + k * BS + lane * 4);
        uint4 u = make_uint4(f2tf(v.x), f2tf(v.y), f2tf(v.z), f2tf(v.w));
        *(uint4*)&Bs[k * PB2 + lane * 4] = u;
    }
    __syncthreads();

    int wm = w >> 1, wn = w & 1, g = lane >> 2, tg = lane & 3;
    int m0 = wm * 32;

    float d[2][8][4];
#pragma unroll
    for (int mi = 0; mi < 2; mi++)
#pragma unroll
        for (int s = 0; s < 8; s++)
#pragma unroll
            for (int j = 0; j < 4; j++) d[mi][s][j] = 0.f;

#pragma unroll
    for (int kk = 0; kk < 16; kk++) {
        int k0 = kk * 8;
        uint32_t a[2][4], b[8][2];
#pragma unroll
        for (int mi = 0; mi < 2; mi++) {
            // A is stored transposed: a(row m, col k) = As[k][m]
            int mb = m0 + mi * 16 + g;
            a[mi][0] = __float_as_uint(As[(k0 + tg) * PA2 + mb]);
            a[mi][1] = __float_as_uint(As[(k0 + tg) * PA2 + mb + 8]);
            a[mi][2] = __float_as_uint(As[(k0 + tg + 4) * PA2 + mb]);
            a[mi][3] = __float_as_uint(As[(k0 + tg + 4) * PA2 + mb + 8]);
        }
#pragma unroll
        for (int s = 0; s < 8; s++) {
            int ncol = wn * 32 + ((s < 4) ? s * 8 : 64 + (s - 4) * 8) + g;
            b[s][0] = __float_as_uint(Bs[(k0 + tg) * PB2 + ncol]);
            b[s][1] = __float_as_uint(Bs[(k0 + tg + 4) * PB2 + ncol]);
        }
#pragma unroll
        for (int mi = 0; mi < 2; mi++)
#pragma unroll
            for (int s = 0; s < 8; s++) mma8(d[mi][s], a[mi], b[s]);
    }

    // epilogue: pair (c2', c2'+64) -> float2 at out[row][q*128 + 2*k2], q = c2'
#pragma unroll
    for (int mi = 0; mi < 2; mi++)
#pragma unroll
        for (int rh = 0; rh < 2; rh++) {
            int row = b0 + m0 + mi * 16 + g + rh * 8;
            if (row < B) {
                float* orow = OUT + (size_t)row * SIZE + 2 * k2;
#pragma unroll
                for (int s = 0; s < 4; s++)
#pragma unroll
                    for (int par = 0; par < 2; par++) {
                        int q = wn * 32 + s * 8 + 2 * tg + par;
                        float2 bv = bsh[q];
                        float2 o = make_float2(d[mi][s][rh * 2 + par] + bv.x,
                                               d[mi][s + 4][rh * 2 + par] + bv.y);
                        *(float2*)(orow + (size_t)q * BS) = o;
                    }
            }
        }
}

// ---------------- launch ----------------
extern "C" void kernel_launch(void* const* d_in, const int* in_sizes, int n_in,
                              void* d_out, int out_size) {
    (void)n_in; (void)out_size;
    const float* x = (const float*)d_in[0];
    const float* w1 = (const float*)d_in[1];
    const float* w2 = (const float*)d_in[2];
    const float* bias = (const float*)d_in[3];
    float* out = (float*)d_out;
    int B = in_sizes[0] / SIZE;
    int mt = (B + 127) / 128;

    cudaFuncSetAttribute(monarch_pass1, cudaFuncAttributeMaxDynamicSharedMemorySize, SMEM1);
    cudaFuncSetAttribute(monarch_pass2, cudaFuncAttributeMaxDynamicSharedMemorySize, SMEM2);

    monarch_pass1<<<dim3(2 * NB, mt), 256, SMEM1>>>(x, w1, B);
    monarch_pass2<<<dim3(NB, mt), 256, SMEM2>>>(w2, bias, out, B);
}

// round 5
// speedup vs baseline: 1.0139x; 1.0139x over previous
#include <cuda_runtime.h>
#include <cstdint>

#define SIZE 8192
#define NB 64
#define BS 128

// Scratch: intermediate in permuted plane layout A2[k2][c2][b] (64*128*4096 floats)
__device__ float g_h[33554432];

__device__ __forceinline__ uint32_t f2tf(float f) {
    uint32_t r;
    asm("cvt.rna.tf32.f32 %0, %1;" : "=r"(r) : "f"(f));
    return r;
}

__device__ __forceinline__ void mma8(float* d, const uint32_t* a, const uint32_t* b) {
    asm volatile(
        "mma.sync.aligned.m16n8k8.row.col.f32.tf32.tf32.f32 "
        "{%0,%1,%2,%3},{%4,%5,%6,%7},{%8,%9},{%0,%1,%2,%3};"
        : "+f"(d[0]), "+f"(d[1]), "+f"(d[2]), "+f"(d[3])
        : "r"(a[0]), "r"(a[1]), "r"(a[2]), "r"(a[3]), "r"(b[0]), "r"(b[1]));
}

// Pads (words): chosen so fragment LDS bank index is a bijection over the warp.
//  pass1 A [m][k]   PA1=132 (132%32==4 -> g*4+tg distinct)
//  pass1 B [k][n]   PB1=72  (72%32==8  -> tg*8+g distinct)
//  pass1 DT [d][b]  PDT=132 (STS banks 8tg+g distinct)
//  pass2 A [c2][b]  PA2=136 (136%32==8 -> tg*8+g distinct)
//  pass2 B [k][lc]  PB2=72
#define PA1 132
#define PB1 72
#define PDT 132
#define PA2 136
#define PB2 72

#define SMEM1 ((128 * PA1 + 128 * PB1) * 4)   // 104448 -> 2 CTAs/SM
#define SMEM2 ((128 * PA2 + 128 * PB2) * 4)   // 106496 -> 2 CTAs/SM

// ---------------- pass 1: per-block GEMM x @ w1, epilogue writes permuted planes ----------------
// CTA (kblk, nh): D[b0:+128][nh*64:+64] for block kblk. Warp tile 64x16.
// Epilogue transposes D in smem and writes planes A2[dg>>1][kblk + 64*(dg&1)][b] coalesced.
__global__ void __launch_bounds__(256, 2) monarch_pass1(const float* __restrict__ X,
                                                        const float* __restrict__ W1, int B) {
    extern __shared__ float sm[];
    float* As = sm;               // [128][PA1]  x tile (m,k)
    float* Bs = sm + 128 * PA1;   // [128][PB1]  w1 slice (k, 64 cols)

    int t = threadIdx.x, lane = t & 31, w = t >> 5;
    int kblk = blockIdx.x >> 1, nh = blockIdx.x & 1;
    int b0 = blockIdx.y * 128;

    // stage A: x[b0:+128][kblk*128:+128], rna tf32
    const float* xp = X + (size_t)b0 * SIZE + kblk * BS;
#pragma unroll
    for (int i = 0; i < 16; i++) {
        int r = i * 8 + w;
        float4 v = make_float4(0.f, 0.f, 0.f, 0.f);
        if (b0 + r < B) v = *(const float4*)(xp + (size_t)r * SIZE + lane * 4);
        uint4 u = make_uint4(f2tf(v.x), f2tf(v.y), f2tf(v.z), f2tf(v.w));
        *(uint4*)&As[r * PA1 + lane * 4] = u;
    }
    // stage B: w1[kblk][0:128][nh*64:+64]
    const float* wp = W1 + kblk * BS * BS + nh * 64;
#pragma unroll
    for (int i = 0; i < 8; i++) {
        int k = i * 16 + (t >> 4);
        float4 v = *(const float4*)(wp + k * BS + (t & 15) * 4);
        uint4 u = make_uint4(f2tf(v.x), f2tf(v.y), f2tf(v.z), f2tf(v.w));
        *(uint4*)&Bs[k * PB1 + (t & 15) * 4] = u;
    }
    __syncthreads();

    int wm = w >> 2, wn = w & 3, g = lane >> 2, tg = lane & 3;
    int m0 = wm * 64, n0 = wn * 16;

    float d[4][2][4];
#pragma unroll
    for (int mi = 0; mi < 4; mi++)
#pragma unroll
        for (int s = 0; s < 2; s++)
#pragma unroll
            for (int j = 0; j < 4; j++) d[mi][s][j] = 0.f;

#pragma unroll
    for (int kk = 0; kk < 16; kk++) {
        int k0 = kk * 8;
        uint32_t a[4][4], b[2][2];
#pragma unroll
        for (int mi = 0; mi < 4; mi++) {
            const float* ap = &As[(m0 + mi * 16 + g) * PA1 + k0 + tg];
            a[mi][0] = __float_as_uint(ap[0]);
            a[mi][1] = __float_as_uint(ap[8 * PA1]);
            a[mi][2] = __float_as_uint(ap[4]);
            a[mi][3] = __float_as_uint(ap[8 * PA1 + 4]);
        }
#pragma unroll
        for (int s = 0; s < 2; s++) {
            const float* bp = &Bs[(k0 + tg) * PB1 + n0 + s * 8 + g];
            b[s][0] = __float_as_uint(bp[0]);
            b[s][1] = __float_as_uint(bp[4 * PB1]);
        }
#pragma unroll
        for (int mi = 0; mi < 4; mi++)
#pragma unroll
            for (int s = 0; s < 2; s++) mma8(d[mi][s], a[mi], b[s]);
    }

    // transpose D in smem: DT[dl][b], dl = local d (0..63)
    __syncthreads();
    float* DT = sm;  // 64*PDT floats, reuses As region
#pragma unroll
    for (int mi = 0; mi < 4; mi++)
#pragma unroll
        for (int s = 0; s < 2; s++) {
            int br = m0 + mi * 16 + g;
            int c0 = n0 + s * 8 + 2 * tg;
            DT[c0 * PDT + br] = d[mi][s][0];
            DT[(c0 + 1) * PDT + br] = d[mi][s][1];
            DT[c0 * PDT + br + 8] = d[mi][s][2];
            DT[(c0 + 1) * PDT + br + 8] = d[mi][s][3];
        }
    __syncthreads();

    // write permuted planes: dg = nh*64+dl -> A2[dg>>1][kblk + 64*(dg&1)][b0..]
    bool okc = (b0 + lane * 4) < B;
#pragma unroll
    for (int i = 0; i < 8; i++) {
        int dl = i * 8 + w;
        int dg = nh * 64 + dl;
        size_t off = ((size_t)(dg >> 1) * BS + (kblk + 64 * (dg & 1))) * (size_t)B + b0 + lane * 4;
        if (okc) *(float4*)(g_h + off) = *(float4*)&DT[dl * PDT + lane * 4];
    }
}

// ---------------- pass 2: per-k2 GEMM A2[k2] @ w2[k2], paired epilogue + bias ----------------
// CTA (k2, nh, mt): q-range [nh*32,+32), B tile stores the 64 needed cols
// (lc<32 -> c2'=q0+lc ; lc>=32 -> c2'=64+q0+lc-32). Warp tile M64 x 16 paired cols.
__global__ void __launch_bounds__(256, 2) monarch_pass2(const float* __restrict__ W2,
                                                        const float* __restrict__ bias,
                                                        float* __restrict__ OUT, int B) {
    extern __shared__ float sm[];
    float* As = sm;               // [128][PA2]  AT (c2, b)
    float* Bs = sm + 128 * PA2;   // [128][PB2]  w2[k2] selected 64 cols
    __shared__ float2 bsh[32];

    int t = threadIdx.x, lane = t & 31, w = t >> 5;
    int k2 = blockIdx.x >> 1, nh = blockIdx.x & 1;
    int q0 = nh * 32;
    int b0 = blockIdx.y * 128;

    if (t < 32) bsh[t] = *(const float2*)(bias + (q0 + t) * BS + 2 * k2);

    // stage A: plane k2, rows c2 = 0..127, cols b0..+127 (coalesced 512B rows)
    const float* ap = g_h + (size_t)k2 * BS * (size_t)B + b0;
    bool okc = (b0 + lane * 4) < B;
#pragma unroll
    for (int i = 0; i < 16; i++) {
        int c2 = i * 8 + w;
        float4 v = make_float4(0.f, 0.f, 0.f, 0.f);
        if (okc) v = *(const float4*)(ap + (size_t)c2 * B + lane * 4);
        uint4 u = make_uint4(f2tf(v.x), f2tf(v.y), f2tf(v.z), f2tf(v.w));
        *(uint4*)&As[c2 * PA2 + lane * 4] = u;
    }
    // stage B: w2[k2][k][cols q0..q0+31 and 64+q0..64+q0+31]
    {
        const float* wp = W2 + k2 * BS * BS;
        int fl = t & 15;
        int gcol = (fl < 8) ? (q0 + fl * 4) : (64 + q0 + (fl - 8) * 4);
#pragma unroll
        for (int i = 0; i < 8; i++) {
            int k = i * 16 + (t >> 4);
            float4 v = *(const float4*)(wp + k * BS + gcol);
            uint4 u = make_uint4(f2tf(v.x), f2tf(v.y), f2tf(v.z), f2tf(v.w));
            *(uint4*)&Bs[k * PB2 + fl * 4] = u;
        }
    }
    __syncthreads();

    int wm = w >> 2, wn = w & 3, g = lane >> 2, tg = lane & 3;
    int m0 = wm * 64;

    float d[4][2][4];
#pragma unroll
    for (int mi = 0; mi < 4; mi++)
#pragma unroll
        for (int s = 0; s < 2; s++)
#pragma unroll
            for (int j = 0; j < 4; j++) d[mi][s][j] = 0.f;

#pragma unroll
    for (int kk = 0; kk < 16; kk++) {
        int k0 = kk * 8;
        uint32_t a[4][4], b[2][2];
#pragma unroll
        for (int mi = 0; mi < 4; mi++) {
            // A stored transposed: a(m,k) = As[k][m]
            int mb = m0 + mi * 16 + g;
            a[mi][0] = __float_as_uint(As[(k0 + tg) * PA2 + mb]);
            a[mi][1] = __float_as_uint(As[(k0 + tg) * PA2 + mb + 8]);
            a[mi][2] = __float_as_uint(As[(k0 + tg + 4) * PA2 + mb]);
            a[mi][3] = __float_as_uint(As[(k0 + tg + 4) * PA2 + mb + 8]);
        }
#pragma unroll
        for (int s = 0; s < 2; s++) {
            int lc = s * 32 + wn * 8 + g;
            b[s][0] = __float_as_uint(Bs[(k0 + tg) * PB2 + lc]);
            b[s][1] = __float_as_uint(Bs[(k0 + tg + 4) * PB2 + lc]);
        }
#pragma unroll
        for (int mi = 0; mi < 4; mi++)
#pragma unroll
            for (int s = 0; s < 2; s++) mma8(d[mi][s], a[mi], b[s]);
    }

    // epilogue: pair (c2'=q, c2'=q+64) -> float2 at out[row][q*128 + 2*k2]
#pragma unroll
    for (int mi = 0; mi < 4; mi++)
#pragma unroll
        for (int rh = 0; rh < 2; rh++) {
            int row = b0 + m0 + mi * 16 + g + rh * 8;
            if (row < B) {
                float* orow = OUT + (size_t)row * SIZE + 2 * k2;
#pragma unroll
                for (int par = 0; par < 2; par++) {
                    int ql = wn * 8 + 2 * tg + par;       // 0..31
                    float2 bv = bsh[ql];
                    float2 o = make_float2(d[mi][0][rh * 2 + par] + bv.x,
                                           d[mi][1][rh * 2 + par] + bv.y);
                    *(float2*)(orow + (size_t)(q0 + ql) * BS) = o;
                }
            }
        }
}

// ---------------- launch ----------------
extern "C" void kernel_launch(void* const* d_in, const int* in_sizes, int n_in,
                              void* d_out, int out_size) {
    (void)n_in; (void)out_size;
    const float* x = (const float*)d_in[0];
    const float* w1 = (const float*)d_in[1];
    const float* w2 = (const float*)d_in[2];
    const float* bias = (const float*)d_in[3];
    float* out = (float*)d_out;
    int B = in_sizes[0] / SIZE;
    int mt = (B + 127) / 128;

    cudaFuncSetAttribute(monarch_pass1, cudaFuncAttributeMaxDynamicSharedMemorySize, SMEM1);
    cudaFuncSetAttribute(monarch_pass2, cudaFuncAttributeMaxDynamicSharedMemorySize, SMEM2);

    monarch_pass1<<<dim3(2 * NB, mt), 256, SMEM1>>>(x, w1, B);
    monarch_pass2<<<dim3(2 * NB, mt), 256, SMEM2>>>(w2, bias, out, B);
}

// round 6
// speedup vs baseline: 1.1099x; 1.0947x over previous
#include <cuda_runtime.h>
#include <cstdint>

#define SIZE 8192
#define NB 64
#define BS 128

// Scratch: intermediate (tf32-rounded) in permuted plane layout A2[k2][c2][b]
__device__ float g_h[33554432];
// tf32-rounded weights
__device__ float g_w1r[NB * BS * BS];
__device__ float g_w2r[NB * BS * BS];

__device__ __forceinline__ uint32_t smem_u32(const void* p) {
    uint32_t a;
    asm("{ .reg .u64 t; cvta.to.shared.u64 t, %1; cvt.u32.u64 %0, t; }" : "=r"(a) : "l"(p));
    return a;
}
__device__ __forceinline__ uint32_t f2tf(float f) {
    uint32_t r;
    asm("cvt.rna.tf32.f32 %0, %1;" : "=r"(r) : "f"(f));
    return r;
}
__device__ __forceinline__ void cpa16(uint32_t s, const float* g) {
    asm volatile("cp.async.cg.shared.global [%0], [%1], 16;" :: "r"(s), "l"(g));
}
#define CPA_COMMIT() asm volatile("cp.async.commit_group;" ::: "memory")
#define CPA_WAIT(n)  asm volatile("cp.async.wait_group %0;" :: "n"(n) : "memory")

__device__ __forceinline__ void mma8(float* d, const uint32_t* a, const uint32_t* b) {
    asm volatile(
        "mma.sync.aligned.m16n8k8.row.col.f32.tf32.tf32.f32 "
        "{%0,%1,%2,%3},{%4,%5,%6,%7},{%8,%9},{%0,%1,%2,%3};"
        : "+f"(d[0]), "+f"(d[1]), "+f"(d[2]), "+f"(d[3])
        : "r"(a[0]), "r"(a[1]), "r"(a[2]), "r"(a[3]), "r"(b[0]), "r"(b[1]));
}

// Pads (words): fragment LDS bank bijections.
#define PA1 132   // pass1 A [m][k]: 132%32==4  -> 4g+tg
#define PB1 72    // pass1 B [k][n]: 72%32==8   -> 8tg+g
#define PDT 132   // pass1 DT[d][b] STS: 8tg+g
#define PA2 136   // pass2 A [c2][b]: 136%32==8 -> 8tg+g
#define PB2 72    // pass2 B [c2][lc]: 8tg+g

#define SMEM1 ((128 * PA1 + 128 * PB1) * 4)            // 104448 -> 2 CTAs/SM
#define SMEM2 ((2 * 32 * PA2 + 2 * 32 * PB2) * 4)      // 53248  -> 3 CTAs/SM

// ---------------- prep: tf32-round weights ----------------
__global__ void prep_cvt(const float* __restrict__ w1, const float* __restrict__ w2) {
    int i = blockIdx.x * 256 + threadIdx.x;           // over 512K float4
    const int HALF = NB * BS * BS / 4;                // 256K float4 per weight
    const float4* src = (i < HALF) ? (const float4*)w1 : (const float4*)w2;
    float* dst = (i < HALF) ? g_w1r : g_w2r;
    int j = (i < HALF) ? i : i - HALF;
    float4 v = src[j];
    uint4 u = make_uint4(f2tf(v.x), f2tf(v.y), f2tf(v.z), f2tf(v.w));
    *(uint4*)(dst + j * 4) = u;
}

// ---------------- pass 1: per-block GEMM x @ w1, epilogue writes rounded permuted planes ----------------
__global__ void __launch_bounds__(256, 2) monarch_pass1(const float* __restrict__ X, int B) {
    extern __shared__ float sm[];
    float* As = sm;               // [128][PA1]
    float* Bs = sm + 128 * PA1;   // [128][PB1]
    uint32_t sb = smem_u32(sm);

    int t = threadIdx.x, lane = t & 31, w = t >> 5;
    int kblk = blockIdx.x >> 1, nh = blockIdx.x & 1;
    int b0 = blockIdx.y * 128;

    // issue B via cp.async first (overlaps with A cvt-stage): w1r[kblk][k][nh*64 + n]
    {
        const float* wr = g_w1r + kblk * BS * BS + nh * 64;
#pragma unroll
        for (int i = 0; i < 8; i++) {
            int idx = t + i * 256;
            int row = idx >> 4, c16 = idx & 15;
            cpa16(sb + (uint32_t)(128 * PA1 + row * PB1 + c16 * 4) * 4,
                  wr + row * BS + c16 * 4);
        }
        CPA_COMMIT();
    }

    // stage A: x[b0:+128][kblk*128:+128], rna tf32
    const float* xp = X + (size_t)b0 * SIZE + kblk * BS;
#pragma unroll
    for (int i = 0; i < 16; i++) {
        int r = i * 8 + w;
        float4 v = make_float4(0.f, 0.f, 0.f, 0.f);
        if (b0 + r < B) v = *(const float4*)(xp + (size_t)r * SIZE + lane * 4);
        uint4 u = make_uint4(f2tf(v.x), f2tf(v.y), f2tf(v.z), f2tf(v.w));
        *(uint4*)&As[r * PA1 + lane * 4] = u;
    }
    CPA_WAIT(0);
    __syncthreads();

    // warp map: wm = w&3 (m0 = wm*32), wn = w>>2 (n0 = wn*32); 32x32 warp tile
    int wm = w & 3, wn = w >> 2, g = lane >> 2, tg = lane & 3;
    int m0 = wm * 32, n0 = wn * 32;

    float d[2][4][4];
#pragma unroll
    for (int mi = 0; mi < 2; mi++)
#pragma unroll
        for (int s = 0; s < 4; s++)
#pragma unroll
            for (int j = 0; j < 4; j++) d[mi][s][j] = 0.f;

#pragma unroll
    for (int kk = 0; kk < 16; kk++) {
        int k0 = kk * 8;
        uint32_t a[2][4], b[4][2];
#pragma unroll
        for (int mi = 0; mi < 2; mi++) {
            const float* ap = &As[(m0 + mi * 16 + g) * PA1 + k0 + tg];
            a[mi][0] = __float_as_uint(ap[0]);
            a[mi][1] = __float_as_uint(ap[8 * PA1]);
            a[mi][2] = __float_as_uint(ap[4]);
            a[mi][3] = __float_as_uint(ap[8 * PA1 + 4]);
        }
#pragma unroll
        for (int s = 0; s < 4; s++) {
            const float* bp = &Bs[(k0 + tg) * PB1 + n0 + s * 8 + g];
            b[s][0] = __float_as_uint(bp[0]);
            b[s][1] = __float_as_uint(bp[4 * PB1]);
        }
#pragma unroll
        for (int mi = 0; mi < 2; mi++)
#pragma unroll
            for (int s = 0; s < 4; s++) mma8(d[mi][s], a[mi], b[s]);
    }

    // transpose D in smem (tf32-rounded): DT[dl][b]
    __syncthreads();
    float* DT = sm;  // 64*PDT floats
#pragma unroll
    for (int mi = 0; mi < 2; mi++)
#pragma unroll
        for (int s = 0; s < 4; s++) {
            int br = m0 + mi * 16 + g;
            int c0 = n0 + s * 8 + 2 * tg;
            DT[c0 * PDT + br] = __uint_as_float(f2tf(d[mi][s][0]));
            DT[(c0 + 1) * PDT + br] = __uint_as_float(f2tf(d[mi][s][1]));
            DT[c0 * PDT + br + 8] = __uint_as_float(f2tf(d[mi][s][2]));
            DT[(c0 + 1) * PDT + br + 8] = __uint_as_float(f2tf(d[mi][s][3]));
        }
    __syncthreads();

    // write permuted planes: dg = nh*64+dl -> A2[dg>>1][kblk + 64*(dg&1)][b0..]
    bool okc = (b0 + lane * 4) < B;
#pragma unroll
    for (int i = 0; i < 8; i++) {
        int dl = i * 8 + w;
        int dg = nh * 64 + dl;
        size_t off = ((size_t)(dg >> 1) * BS + (kblk + 64 * (dg & 1))) * (size_t)B + b0 + lane * 4;
        if (okc) *(float4*)(g_h + off) = *(float4*)&DT[dl * PDT + lane * 4];
    }
}

// ---------------- pass 2: per-k2 GEMM A2[k2] @ w2[k2], cp.async K-chunk pipeline ----------------
// CTA (k2, nh, mt). K = 128 split into 4 chunks of 32 c2-rows, double-buffered.
// Warp tile 32x32 (wm = w&3 -> m0, wn = w>>2 -> 16 q-pairs). Paired epilogue + bias.
__global__ void __launch_bounds__(256, 3) monarch_pass2(const float* __restrict__ bias,
                                                        float* __restrict__ OUT, int B) {
    extern __shared__ float sm[];
    uint32_t sb = smem_u32(sm);
    __shared__ float2 bsh[32];

    int t = threadIdx.x, lane = t & 31, w = t >> 5;
    int k2 = blockIdx.x >> 1, nh = blockIdx.x & 1;
    int q0 = nh * 32;
    int b0 = blockIdx.y * 128;

    if (t < 32) bsh[t] = *(const float2*)(bias + (q0 + t) * BS + 2 * k2);

    const float* ap = g_h + (size_t)k2 * BS * (size_t)B + b0;   // row stride B
    const float* wp = g_w2r + k2 * BS * BS;

    // chunk issue: A chunk [32][128] (16KB), B chunk [32][64 sel cols] (8KB)
    int arow = t >> 5, ac16 = t & 31;                  // A: idx = t + i*256 -> row += 8
    int brow = t >> 4, bc16 = t & 15;                  // B: idx = t + i*256 -> row += 16
    int blc = bc16 * 4;
    int bsc = q0 + blc + ((blc >= 32) ? 32 : 0);       // source column in w2 row

#define ISSUE_CHUNK(c, buf) do {                                                        \
        uint32_t abase = sb + (uint32_t)((buf) * 32 * PA2) * 4;                          \
        uint32_t bbase = sb + (uint32_t)(2 * 32 * PA2 + (buf) * 32 * PB2) * 4;           \
        _Pragma("unroll")                                                                \
        for (int i = 0; i < 4; i++) {                                                    \
            int row = arow + i * 8;                                                      \
            cpa16(abase + (uint32_t)(row * PA2 + ac16 * 4) * 4,                          \
                  ap + (size_t)((c) * 32 + row) * B + ac16 * 4);                         \
        }                                                                                \
        _Pragma("unroll")                                                                \
        for (int i = 0; i < 2; i++) {                                                    \
            int row = brow + i * 16;                                                     \
            cpa16(bbase + (uint32_t)(row * PB2 + blc) * 4,                               \
                  wp + ((c) * 32 + row) * BS + bsc);                                     \
        }                                                                                \
        CPA_COMMIT();                                                                    \
    } while (0)

    ISSUE_CHUNK(0, 0);
    ISSUE_CHUNK(1, 1);

    int wm = w & 3, wn = w >> 2, g = lane >> 2, tg = lane & 3;
    int m0 = wm * 32;

    float d[2][4][4];
#pragma unroll
    for (int mi = 0; mi < 2; mi++)
#pragma unroll
        for (int s = 0; s < 4; s++)
#pragma unroll
            for (int j = 0; j < 4; j++) d[mi][s][j] = 0.f;

#pragma unroll
    for (int c = 0; c < 4; c++) {
        if (c == 3) { CPA_WAIT(0); } else { CPA_WAIT(1); }
        __syncthreads();
        const float* Abuf = sm + (c & 1) * 32 * PA2;
        const float* Bbuf = sm + 2 * 32 * PA2 + (c & 1) * 32 * PB2;
#pragma unroll
        for (int kk = 0; kk < 4; kk++) {
            int k0 = kk * 8;
            uint32_t a[2][4], b[4][2];
#pragma unroll
            for (int mi = 0; mi < 2; mi++) {
                int mb = m0 + mi * 16 + g;
                a[mi][0] = __float_as_uint(Abuf[(k0 + tg) * PA2 + mb]);
                a[mi][1] = __float_as_uint(Abuf[(k0 + tg) * PA2 + mb + 8]);
                a[mi][2] = __float_as_uint(Abuf[(k0 + tg + 4) * PA2 + mb]);
                a[mi][3] = __float_as_uint(Abuf[(k0 + tg + 4) * PA2 + mb + 8]);
            }
#pragma unroll
            for (int s = 0; s < 4; s++) {
                int lc = (s < 2) ? (wn * 16 + s * 8 + g) : (32 + wn * 16 + (s - 2) * 8 + g);
                b[s][0] = __float_as_uint(Bbuf[(k0 + tg) * PB2 + lc]);
                b[s][1] = __float_as_uint(Bbuf[(k0 + tg + 4) * PB2 + lc]);
            }
#pragma unroll
            for (int mi = 0; mi < 2; mi++)
#pragma unroll
                for (int s = 0; s < 4; s++) mma8(d[mi][s], a[mi], b[s]);
        }
        __syncthreads();
        if (c == 0) ISSUE_CHUNK(2, 0);
        if (c == 1) ISSUE_CHUNK(3, 1);
    }

    // epilogue: pair (q, q+64) -> float2 at out[row][q*128 + 2*k2]
#pragma unroll
    for (int mi = 0; mi < 2; mi++)
#pragma unroll
        for (int rh = 0; rh < 2; rh++) {
            int row = b0 + m0 + mi * 16 + g + rh * 8;
            if (row < B) {
                float* orow = OUT + (size_t)row * SIZE + 2 * k2;
#pragma unroll
                for (int s2 = 0; s2 < 2; s2++)
#pragma unroll
                    for (int par = 0; par < 2; par++) {
                        int ql = wn * 16 + s2 * 8 + 2 * tg + par;   // 0..31
                        float2 bv = bsh[ql];
                        float2 o = make_float2(d[mi][s2][rh * 2 + par] + bv.x,
                                               d[mi][s2 + 2][rh * 2 + par] + bv.y);
                        *(float2*)(orow + (size_t)(q0 + ql) * BS) = o;
                    }
            }
        }
}

// ---------------- launch ----------------
extern "C" void kernel_launch(void* const* d_in, const int* in_sizes, int n_in,
                              void* d_out, int out_size) {
    (void)n_in; (void)out_size;
    const float* x = (const float*)d_in[0];
    const float* w1 = (const float*)d_in[1];
    const float* w2 = (const float*)d_in[2];
    const float* bias = (const float*)d_in[3];
    float* out = (float*)d_out;
    int B = in_sizes[0] / SIZE;
    int mt = (B + 127) / 128;

    cudaFuncSetAttribute(monarch_pass1, cudaFuncAttributeMaxDynamicSharedMemorySize, SMEM1);
    cudaFuncSetAttribute(monarch_pass2, cudaFuncAttributeMaxDynamicSharedMemorySize, SMEM2);

    prep_cvt<<<2048, 256>>>(w1, w2);
    monarch_pass1<<<dim3(2 * NB, mt), 256, SMEM1>>>(x, B);
    monarch_pass2<<<dim3(2 * NB, mt), 256, SMEM2>>>(bias, out, B);
}

// round 7
// speedup vs baseline: 1.4167x; 1.2764x over previous
#include <cuda_runtime.h>
#include <cstdint>

#define SIZE 8192
#define NB 64
#define BS 128

// Scratch: intermediate (tf32-rounded) in permuted plane layout A2[k2][c2][b]
__device__ float g_h[33554432];
// tf32-rounded weights
__device__ float g_w1r[NB * BS * BS];
__device__ float g_w2r[NB * BS * BS];

__device__ __forceinline__ uint32_t smem_u32(const void* p) {
    uint32_t a;
    asm("{ .reg .u64 t; cvta.to.shared.u64 t, %1; cvt.u32.u64 %0, t; }" : "=r"(a) : "l"(p));
    return a;
}
__device__ __forceinline__ uint32_t f2tf(float f) {
    uint32_t r;
    asm("cvt.rna.tf32.f32 %0, %1;" : "=r"(r) : "f"(f));
    return r;
}
__device__ __forceinline__ void cpa16(uint32_t s, const float* g) {
    asm volatile("cp.async.cg.shared.global [%0], [%1], 16;" :: "r"(s), "l"(g));
}
__device__ __forceinline__ void sts_zero16(uint32_t s) {
    asm volatile("st.shared.v4.b32 [%0], {%1,%1,%1,%1};" :: "r"(s), "r"(0u));
}
#define CPA_COMMIT() asm volatile("cp.async.commit_group;" ::: "memory")
#define CPA_WAIT(n)  asm volatile("cp.async.wait_group %0;" :: "n"(n) : "memory")

__device__ __forceinline__ void mma8(float* d, const uint32_t* a, const uint32_t* b) {
    asm volatile(
        "mma.sync.aligned.m16n8k8.row.col.f32.tf32.tf32.f32 "
        "{%0,%1,%2,%3},{%4,%5,%6,%7},{%8,%9},{%0,%1,%2,%3};"
        : "+f"(d[0]), "+f"(d[1]), "+f"(d[2]), "+f"(d[3])
        : "r"(a[0]), "r"(a[1]), "r"(a[2]), "r"(a[3]), "r"(b[0]), "r"(b[1]));
}

// Pads (words): fragment LDS bank bijections.
#define PA1 36    // pass1 A chunk [128 m][32 k]: 36%32==4 -> 4m+tg -> 4g+tg distinct
#define PB1 72    // pass1 B chunk [32 k][64 n]: 72%32==8  -> 8tg+g distinct
#define PDT 132   // pass1 DT[d][b] STS: 8tg+g distinct
#define PA2 136   // pass2 A chunk [32 c2][128 b]: 136%32==8 -> 8tg+g distinct
#define PB2 72    // pass2 B chunk [32 c2][64 lc]: 8tg+g distinct

#define SMEM1 ((2 * 128 * PA1 + 2 * 32 * PB1) * 4)   // 55296 -> 2 CTAs/SM
#define SMEM2 ((2 * 32 * PA2 + 2 * 32 * PB2) * 4)    // 53248 -> 2 CTAs/SM

// ---------------- prep: tf32-round weights ----------------
__global__ void prep_cvt(const float* __restrict__ w1, const float* __restrict__ w2) {
    int i = blockIdx.x * 256 + threadIdx.x;
    const int HALF = NB * BS * BS / 4;
    const float4* src = (i < HALF) ? (const float4*)w1 : (const float4*)w2;
    float* dst = (i < HALF) ? g_w1r : g_w2r;
    int j = (i < HALF) ? i : i - HALF;
    float4 v = src[j];
    uint4 u = make_uint4(f2tf(v.x), f2tf(v.y), f2tf(v.z), f2tf(v.w));
    *(uint4*)(dst + j * 4) = u;
}

// ---------------- pass 1: per-block GEMM x @ w1, cp.async pipeline, permuted-plane epilogue ----------------
// CTA (kblk, nh, mt): D[b0:+128][nh*64:+64]. K chunks of 32, double-buffered.
__global__ void __launch_bounds__(256, 2) monarch_pass1(const float* __restrict__ X, int B) {
    extern __shared__ float sm[];
    uint32_t sb = smem_u32(sm);

    int t = threadIdx.x, lane = t & 31, w = t >> 5;
    int kblk = blockIdx.x >> 1, nh = blockIdx.x & 1;
    int b0 = blockIdx.y * 128;

    const float* xp = X + (size_t)b0 * SIZE + kblk * BS;
    const float* wp = g_w1r + kblk * BS * BS + nh * 64;

    // A chunk pieces: 1024 x 16B (row = b, 8 pieces of the 32-k chunk)
    int ar = 0, ac = t & 7;          // row from piece>>3
    int br = 0, bc = t & 15;         // B: 512 pieces, row = piece>>4
    (void)ar; (void)br;

#define P1_ISSUE(c, buf) do {                                                              \
        uint32_t abase = sb + (uint32_t)((buf) * 128 * PA1) * 4;                           \
        uint32_t bbase = sb + (uint32_t)(2 * 128 * PA1 + (buf) * 32 * PB1) * 4;            \
        _Pragma("unroll")                                                                   \
        for (int i = 0; i < 4; i++) {                                                       \
            int piece = t + i * 256;                                                        \
            int row = piece >> 3;                                                           \
            uint32_t dsta = abase + (uint32_t)(row * PA1 + ac * 4) * 4;                     \
            if (b0 + row < B) cpa16(dsta, xp + (size_t)row * SIZE + (c) * 32 + ac * 4);     \
            else sts_zero16(dsta);                                                          \
        }                                                                                   \
        _Pragma("unroll")                                                                   \
        for (int i = 0; i < 2; i++) {                                                       \
            int piece = t + i * 256;                                                        \
            int row = piece >> 4;                                                           \
            cpa16(bbase + (uint32_t)(row * PB1 + bc * 4) * 4,                               \
                  wp + ((c) * 32 + row) * BS + bc * 4);                                     \
        }                                                                                   \
        CPA_COMMIT();                                                                       \
    } while (0)

    P1_ISSUE(0, 0);
    P1_ISSUE(1, 1);

    int wm = w & 3, wn = w >> 2, g = lane >> 2, tg = lane & 3;
    int m0 = wm * 32, n0 = wn * 32;

    float d[2][4][4];
#pragma unroll
    for (int mi = 0; mi < 2; mi++)
#pragma unroll
        for (int s = 0; s < 4; s++)
#pragma unroll
            for (int j = 0; j < 4; j++) d[mi][s][j] = 0.f;

#pragma unroll
    for (int c = 0; c < 4; c++) {
        if (c == 3) { CPA_WAIT(0); } else { CPA_WAIT(1); }
        __syncthreads();
        const float* Abuf = sm + (c & 1) * 128 * PA1;
        const float* Bbuf = sm + 2 * 128 * PA1 + (c & 1) * 32 * PB1;
#pragma unroll
        for (int kk = 0; kk < 4; kk++) {
            int k0 = kk * 8;
            uint32_t a[2][4], b[4][2];
#pragma unroll
            for (int mi = 0; mi < 2; mi++) {
                const float* ap = &Abuf[(m0 + mi * 16 + g) * PA1 + k0 + tg];
                a[mi][0] = f2tf(ap[0]);
                a[mi][1] = f2tf(ap[8 * PA1]);
                a[mi][2] = f2tf(ap[4]);
                a[mi][3] = f2tf(ap[8 * PA1 + 4]);
            }
#pragma unroll
            for (int s = 0; s < 4; s++) {
                const float* bp = &Bbuf[(k0 + tg) * PB1 + n0 + s * 8 + g];
                b[s][0] = __float_as_uint(bp[0]);
                b[s][1] = __float_as_uint(bp[4 * PB1]);
            }
#pragma unroll
            for (int mi = 0; mi < 2; mi++)
#pragma unroll
                for (int s = 0; s < 4; s++) mma8(d[mi][s], a[mi], b[s]);
        }
        __syncthreads();
        if (c == 0) P1_ISSUE(2, 0);
        if (c == 1) P1_ISSUE(3, 1);
    }

    // transpose D in smem (tf32-rounded): DT[dl][b]
    float* DT = sm;  // 64*PDT floats (reuses pipeline buffers; all chunks consumed)
#pragma unroll
    for (int mi = 0; mi < 2; mi++)
#pragma unroll
        for (int s = 0; s < 4; s++) {
            int br2 = m0 + mi * 16 + g;
            int c0 = n0 + s * 8 + 2 * tg;
            DT[c0 * PDT + br2] = __uint_as_float(f2tf(d[mi][s][0]));
            DT[(c0 + 1) * PDT + br2] = __uint_as_float(f2tf(d[mi][s][1]));
            DT[c0 * PDT + br2 + 8] = __uint_as_float(f2tf(d[mi][s][2]));
            DT[(c0 + 1) * PDT + br2 + 8] = __uint_as_float(f2tf(d[mi][s][3]));
        }
    __syncthreads();

    // write permuted planes: dg = nh*64+dl -> A2[dg>>1][kblk + 64*(dg&1)][b0..]
    bool okc = (b0 + lane * 4) < B;
#pragma unroll
    for (int i = 0; i < 8; i++) {
        int dl = i * 8 + w;
        int dg = nh * 64 + dl;
        size_t off = ((size_t)(dg >> 1) * BS + (kblk + 64 * (dg & 1))) * (size_t)B + b0 + lane * 4;
        if (okc) *(float4*)(g_h + off) = *(float4*)&DT[dl * PDT + lane * 4];
    }
}

// ---------------- pass 2: k2-paired GEMMs, cp.async pipeline, STG.128 epilogue ----------------
// CTA (k2g, nh, mt): k2 in {2*k2g, 2*k2g+1}, q-range [nh*32,+32), b rows 128.
// 8 chunks: cc = k2l*4 + c; accumulate into d[k2l]. Epilogue: float4 out cols 4*k2g..+3.
__global__ void __launch_bounds__(256, 2) monarch_pass2(const float* __restrict__ bias,
                                                        float* __restrict__ OUT, int B) {
    extern __shared__ float sm[];
    uint32_t sb = smem_u32(sm);
    __shared__ float4 bsh[32];

    int t = threadIdx.x, lane = t & 31, w = t >> 5;
    int k2g = blockIdx.x >> 1, nh = blockIdx.x & 1;
    int q0 = nh * 32;
    int b0 = blockIdx.y * 128;

    if (t < 32) bsh[t] = *(const float4*)(bias + (q0 + t) * BS + 4 * k2g);

    int ac = t & 31;                 // A: 1024 pieces, row = piece>>5
    int bc16 = t & 15;               // B: 512 pieces, row = piece>>4
    int blc = bc16 * 4;
    int bsc = q0 + blc + ((blc >= 32) ? 32 : 0);   // source col in w2 row
    bool okc = (b0 + ac * 4) < B;

#define P2_ISSUE(cc, buf) do {                                                              \
        int k2s = 2 * k2g + ((cc) >> 2);                                                    \
        int cs = (cc) & 3;                                                                  \
        const float* apb = g_h + (size_t)k2s * BS * (size_t)B + b0;                         \
        const float* wpb = g_w2r + k2s * BS * BS;                                           \
        uint32_t abase = sb + (uint32_t)((buf) * 32 * PA2) * 4;                             \
        uint32_t bbase = sb + (uint32_t)(2 * 32 * PA2 + (buf) * 32 * PB2) * 4;              \
        _Pragma("unroll")                                                                    \
        for (int i = 0; i < 4; i++) {                                                        \
            int piece = t + i * 256;                                                         \
            int row = piece >> 5;                                                            \
            uint32_t dsta = abase + (uint32_t)(row * PA2 + ac * 4) * 4;                      \
            if (okc) cpa16(dsta, apb + (size_t)(cs * 32 + row) * B + ac * 4);                \
            else sts_zero16(dsta);                                                           \
        }                                                                                    \
        _Pragma("unroll")                                                                    \
        for (int i = 0; i < 2; i++) {                                                        \
            int piece = t + i * 256;                                                         \
            int row = piece >> 4;                                                            \
            cpa16(bbase + (uint32_t)(row * PB2 + blc) * 4,                                   \
                  wpb + (cs * 32 + row) * BS + bsc);                                         \
        }                                                                                    \
        CPA_COMMIT();                                                                        \
    } while (0)

    P2_ISSUE(0, 0);
    P2_ISSUE(1, 1);

    int wm = w & 3, wn = w >> 2, g = lane >> 2, tg = lane & 3;
    int m0 = wm * 32;

    float d[2][2][4][4];
#pragma unroll
    for (int kl = 0; kl < 2; kl++)
#pragma unroll
        for (int mi = 0; mi < 2; mi++)
#pragma unroll
            for (int s = 0; s < 4; s++)
#pragma unroll
                for (int j = 0; j < 4; j++) d[kl][mi][s][j] = 0.f;

#pragma unroll
    for (int cc = 0; cc < 8; cc++) {
        if (cc == 7) { CPA_WAIT(0); } else { CPA_WAIT(1); }
        __syncthreads();
        const float* Abuf = sm + (cc & 1) * 32 * PA2;
        const float* Bbuf = sm + 2 * 32 * PA2 + (cc & 1) * 32 * PB2;
        float (*dk)[4][4] = d[cc >> 2];
#pragma unroll
        for (int kk = 0; kk < 4; kk++) {
            int k0 = kk * 8;
            uint32_t a[2][4], b[4][2];
#pragma unroll
            for (int mi = 0; mi < 2; mi++) {
                int mb = m0 + mi * 16 + g;
                a[mi][0] = __float_as_uint(Abuf[(k0 + tg) * PA2 + mb]);
                a[mi][1] = __float_as_uint(Abuf[(k0 + tg) * PA2 + mb + 8]);
                a[mi][2] = __float_as_uint(Abuf[(k0 + tg + 4) * PA2 + mb]);
                a[mi][3] = __float_as_uint(Abuf[(k0 + tg + 4) * PA2 + mb + 8]);
            }
#pragma unroll
            for (int s = 0; s < 4; s++) {
                int lc = (s < 2) ? (wn * 16 + s * 8 + g) : (32 + wn * 16 + (s - 2) * 8 + g);
                b[s][0] = __float_as_uint(Bbuf[(k0 + tg) * PB2 + lc]);
                b[s][1] = __float_as_uint(Bbuf[(k0 + tg + 4) * PB2 + lc]);
            }
#pragma unroll
            for (int mi = 0; mi < 2; mi++)
#pragma unroll
                for (int s = 0; s < 4; s++) mma8(dk[mi][s], a[mi], b[s]);
        }
        __syncthreads();
        if (cc < 6) P2_ISSUE(cc + 2, cc & 1);
    }

    // epilogue: float4 at out[row][q*128 + 4*k2g] = {k2l0(par0,par1), k2l1(par0,par1)} + bias
#pragma unroll
    for (int mi = 0; mi < 2; mi++)
#pragma unroll
        for (int rh = 0; rh < 2; rh++) {
            int row = b0 + m0 + mi * 16 + g + rh * 8;
            if (row < B) {
                float* orow = OUT + (size_t)row * SIZE + 4 * k2g;
#pragma unroll
                for (int s2 = 0; s2 < 2; s2++)
#pragma unroll
                    for (int par = 0; par < 2; par++) {
                        int ql = wn * 16 + s2 * 8 + 2 * tg + par;   // 0..31
                        float4 bv = bsh[ql];
                        float4 o;
                        o.x = d[0][mi][s2][rh * 2 + par] + bv.x;
                        o.y = d[0][mi][s2 + 2][rh * 2 + par] + bv.y;
                        o.z = d[1][mi][s2][rh * 2 + par] + bv.z;
                        o.w = d[1][mi][s2 + 2][rh * 2 + par] + bv.w;
                        *(float4*)(orow + (size_t)(q0 + ql) * BS) = o;
                    }
            }
        }
}

// ---------------- launch ----------------
extern "C" void kernel_launch(void* const* d_in, const int* in_sizes, int n_in,
                              void* d_out, int out_size) {
    (void)n_in; (void)out_size;
    const float* x = (const float*)d_in[0];
    const float* w1 = (const float*)d_in[1];
    const float* w2 = (const float*)d_in[2];
    const float* bias = (const float*)d_in[3];
    float* out = (float*)d_out;
    int B = in_sizes[0] / SIZE;
    int mt = (B + 127) / 128;

    cudaFuncSetAttribute(monarch_pass1, cudaFuncAttributeMaxDynamicSharedMemorySize, SMEM1);
    cudaFuncSetAttribute(monarch_pass2, cudaFuncAttributeMaxDynamicSharedMemorySize, SMEM2);

    prep_cvt<<<2048, 256>>>(w1, w2);
    monarch_pass1<<<dim3(2 * NB, mt), 256, SMEM1>>>(x, B);
    monarch_pass2<<<dim3(NB, mt), 256, SMEM2>>>(bias, out, B);
}

// round 9
// speedup vs baseline: 1.5185x; 1.0718x over previous
#include <cuda_runtime.h>
#include <cstdint>

#define SIZE 8192
#define NB 64
#define BS 128

// g_h: fragment-packed intermediate: [k2][mt][cs][1024 grp][4]
__device__ float g_h[33554432];
// packed weights: w1p [kblk][cs][1024 grp][4], w2p [k2][nh][cs][512 grp][4]
__device__ float g_w1p[1048576];
__device__ float g_w2p[1048576];

__device__ __forceinline__ uint32_t smem_u32(const void* p) {
    uint32_t a;
    asm("{ .reg .u64 t; cvta.to.shared.u64 t, %1; cvt.u32.u64 %0, t; }" : "=r"(a) : "l"(p));
    return a;
}
__device__ __forceinline__ uint32_t f2tf(float f) {
    uint32_t r;
    asm("cvt.rna.tf32.f32 %0, %1;" : "=r"(r) : "f"(f));
    return r;
}
__device__ __forceinline__ float f2tff(float f) { return __uint_as_float(f2tf(f)); }
__device__ __forceinline__ void cpa16(uint32_t s, const float* g) {
    asm volatile("cp.async.cg.shared.global [%0], [%1], 16;" :: "r"(s), "l"(g));
}
__device__ __forceinline__ void sts_zero16(uint32_t s) {
    asm volatile("st.shared.v4.b32 [%0], {%1,%1,%1,%1};" :: "r"(s), "r"(0u));
}
#define CPA_COMMIT() asm volatile("cp.async.commit_group;" ::: "memory")
#define CPA_WAIT(n)  asm volatile("cp.async.wait_group %0;" :: "n"(n) : "memory")

__device__ __forceinline__ void mma8(float* d, const uint32_t* a, const uint32_t* b) {
    asm volatile(
        "mma.sync.aligned.m16n8k8.row.col.f32.tf32.tf32.f32 "
        "{%0,%1,%2,%3},{%4,%5,%6,%7},{%8,%9},{%0,%1,%2,%3};"
        : "+f"(d[0]), "+f"(d[1]), "+f"(d[2]), "+f"(d[3])
        : "r"(a[0]), "r"(a[1]), "r"(a[2]), "r"(a[3]), "r"(b[0]), "r"(b[1]));
}

// pass1 A pad (scalar LDS): 36%32==4 -> banks 4g+tg bijective
#define PA1 36
#define SMEM1 ((3 * 128 * PA1 + 3 * 4096) * 4)     // 104448 B (2 CTAs/SM: 204KB <= 228KB)
#define SMEM2 ((3 * 4096 + 3 * 2048) * 4)          // 73728 B  (2 CTAs/SM)
#define SMEMP (128 * 132 * 4)                      // 67584 B (prep)

// ---------------- prep: pack tf32-rounded weights into fragment-group layout ----------------
// w1p grp = (((kk*4+u)*2+wn)*8+g)*4 + tg ; elems [(klo,l0),(khi,l0),(klo,l0+8),(khi,l0+8)]
//   klo = kk*8+tg (+4 = khi), rows = cs*32 + slot, l0 = wn*64 + u*16 + g
// w2p grp = (((kk*2+u)*2+wn)*8+g)*4 + tg ; rows via slot->c2 map: c2 = cs*16+kk*4+tg (+64 for khi)
//   l0 = wn*16 + u*32 + g ; source col: lc<32 -> q0+lc else 32+q0+lc
__global__ void prep_pack(const float* __restrict__ w1, const float* __restrict__ w2) {
    extern __shared__ float ps[];
    int t = threadIdx.x;
    int cid = blockIdx.x;
    if (cid < 64) {
        int kblk = cid;
        const float4* src = (const float4*)(w1 + kblk * BS * BS);
#pragma unroll
        for (int i = 0; i < 16; i++) {
            int idx = t + i * 256;
            int row = idx >> 5, c4 = idx & 31;
            float4 v = src[idx];
            float4 o = make_float4(f2tff(v.x), f2tff(v.y), f2tff(v.z), f2tff(v.w));
            *(float4*)(ps + row * 132 + c4 * 4) = o;
        }
        __syncthreads();
#pragma unroll
        for (int i = 0; i < 16; i++) {
            int gidx = t + i * 256;
            int cs = gidx >> 10, grp = gidx & 1023;
            int tg = grp & 3, g = (grp >> 2) & 7, wn = (grp >> 5) & 1, u = (grp >> 6) & 3, kk = grp >> 8;
            int rlo = cs * 32 + kk * 8 + tg, rhi = rlo + 4;
            int l0 = wn * 64 + u * 16 + g;
            float4 o = make_float4(ps[rlo * 132 + l0], ps[rhi * 132 + l0],
                                   ps[rlo * 132 + l0 + 8], ps[rhi * 132 + l0 + 8]);
            *(float4*)(g_w1p + (size_t)(kblk * 4 + cs) * 4096 + grp * 4) = o;
        }
    } else {
        int k2 = (cid - 64) >> 1, nh = (cid - 64) & 1, q0 = nh * 32;
        const float* src = w2 + k2 * BS * BS;
#pragma unroll
        for (int i = 0; i < 8; i++) {
            int idx = t + i * 256;       // 2048 float4 over [128 rows][64 sel cols]
            int row = idx >> 4, c4 = idx & 15;
            int lc = c4 * 4;
            int sc = (lc < 32) ? (q0 + lc) : (32 + q0 + lc);
            float4 v = *(const float4*)(src + row * BS + sc);
            float4 o = make_float4(f2tff(v.x), f2tff(v.y), f2tff(v.z), f2tff(v.w));
            *(float4*)(ps + row * 68 + lc) = o;
        }
        __syncthreads();
#pragma unroll
        for (int i = 0; i < 8; i++) {
            int gidx = t + i * 256;      // 2048 groups
            int cs = gidx >> 9, grp = gidx & 511;
            int tg = grp & 3, g = (grp >> 2) & 7, wn = (grp >> 5) & 1, u = (grp >> 6) & 1, kk = grp >> 7;
            int rlo = cs * 16 + kk * 4 + tg, rhi = rlo + 64;
            int l0 = wn * 16 + u * 32 + g;
            float4 o = make_float4(ps[rlo * 68 + l0], ps[rhi * 68 + l0],
                                   ps[rlo * 68 + l0 + 8], ps[rhi * 68 + l0 + 8]);
            *(float4*)(g_w2p + (size_t)((k2 * 2 + nh) * 4 + cs) * 2048 + grp * 4) = o;
        }
    }
}

// ---------------- pass 1: CTA (kblk, mt): D[128 b][128 n], 3-stage cp.async, packed epilogue ----------------
__global__ void __launch_bounds__(256, 2) monarch_pass1(const float* __restrict__ X, int Btok, int nmt) {
    extern __shared__ float sm[];
    uint32_t sb = smem_u32(sm);

    int t = threadIdx.x, lane = t & 31, w = t >> 5;
    int kblk = blockIdx.x, mt = blockIdx.y, b0 = mt * 128;
    const float* xp = X + (size_t)b0 * SIZE + kblk * BS;
    const float* bp1 = g_w1p + (size_t)kblk * 4 * 4096;

#define P1_ISSUE(c) do { int st = (c) % 3;                                                   \
        uint32_t ab = sb + (uint32_t)(st * 128 * PA1) * 4;                                   \
        uint32_t bb = sb + (uint32_t)(3 * 128 * PA1 + st * 4096) * 4;                        \
        _Pragma("unroll")                                                                     \
        for (int i = 0; i < 4; i++) {                                                         \
            int p = t + i * 256;                                                              \
            int row = p >> 3, pc = p & 7;                                                     \
            uint32_t dst = ab + (uint32_t)(row * PA1 + pc * 4) * 4;                           \
            if (b0 + row < Btok) cpa16(dst, xp + (size_t)row * SIZE + (c) * 32 + pc * 4);     \
            else sts_zero16(dst);                                                             \
        }                                                                                     \
        _Pragma("unroll")                                                                     \
        for (int i = 0; i < 4; i++) {                                                         \
            int p = t + i * 256;                                                              \
            cpa16(bb + (uint32_t)p * 16, bp1 + (c) * 4096 + p * 4);                           \
        }                                                                                     \
        CPA_COMMIT();                                                                         \
    } while (0)

    P1_ISSUE(0);
    P1_ISSUE(1);

    int wm = w & 3, wn = w >> 2, g = lane >> 2, tg = lane & 3;
    int m0 = wm * 32;

    float d[2][8][4];
#pragma unroll
    for (int mi = 0; mi < 2; mi++)
#pragma unroll
        for (int s = 0; s < 8; s++)
#pragma unroll
            for (int j = 0; j < 4; j++) d[mi][s][j] = 0.f;

#pragma unroll
    for (int c = 0; c < 4; c++) {
        if (c == 3) { CPA_WAIT(0); } else { CPA_WAIT(1); }   // FIX: drain final chunk
        __syncthreads();
        if (c < 2) P1_ISSUE(c + 2);
        const float* Ab = sm + (c % 3) * 128 * PA1;
        const float* Bb = sm + 3 * 128 * PA1 + (c % 3) * 4096;
#pragma unroll
        for (int kk = 0; kk < 4; kk++) {
            uint32_t a[2][4];
#pragma unroll
            for (int mi = 0; mi < 2; mi++) {
                int mb = m0 + mi * 16 + g, kb = kk * 8 + tg;
                a[mi][0] = f2tf(Ab[mb * PA1 + kb]);
                a[mi][1] = f2tf(Ab[(mb + 8) * PA1 + kb]);
                a[mi][2] = f2tf(Ab[mb * PA1 + kb + 4]);
                a[mi][3] = f2tf(Ab[(mb + 8) * PA1 + kb + 4]);
            }
#pragma unroll
            for (int u = 0; u < 4; u++) {
                uint4 bv = *(const uint4*)(Bb + ((((kk * 4 + u) * 2 + wn) * 8 + g) * 4 + tg) * 4);
                uint32_t blo[2] = {bv.x, bv.y}, bhi[2] = {bv.z, bv.w};
                mma8(d[0][2 * u], a[0], blo);
                mma8(d[1][2 * u], a[1], blo);
                mma8(d[0][2 * u + 1], a[0], bhi);
                mma8(d[1][2 * u + 1], a[1], bhi);
            }
        }
    }

    // epilogue: each (mi,s) is one full fragment group {d0,d2,d1,d3} -> STG.128 to g_h packed
    int kk1 = (kblk >> 2) & 3, tg1 = kblk & 3, cs1 = kblk >> 4;
#pragma unroll
    for (int mi = 0; mi < 2; mi++) {
        int grp = ((kk1 * 8 + wm * 2 + mi) * 8 + g) * 4 + tg1;
#pragma unroll
        for (int s = 0; s < 8; s++) {
            int k2 = wn * 32 + s * 4 + tg;
            size_t base = ((size_t)(k2 * nmt + mt) * 4 + cs1) * 4096;
            float4 o = make_float4(f2tff(d[mi][s][0]), f2tff(d[mi][s][2]),
                                   f2tff(d[mi][s][1]), f2tff(d[mi][s][3]));
            *(float4*)(g_h + base + grp * 4) = o;
        }
    }
}

// ---------------- pass 2: CTA (k2g, nh, mt): k2 pair, 8 packed chunks, paired STG.128 epilogue ----------------
__global__ void __launch_bounds__(256, 2) monarch_pass2(const float* __restrict__ bias,
                                                        float* __restrict__ OUT, int Btok, int nmt) {
    extern __shared__ float sm[];
    uint32_t sb = smem_u32(sm);
    __shared__ float4 bsh[32];

    int t = threadIdx.x, lane = t & 31, w = t >> 5;
    int k2g = blockIdx.x >> 1, nh = blockIdx.x & 1;
    int q0 = nh * 32;
    int mt = blockIdx.y, b0 = mt * 128;

    if (t < 32) bsh[t] = *(const float4*)(bias + (q0 + t) * BS + 4 * k2g);

#define P2_ISSUE(cc) do { int st = (cc) % 3;                                                  \
        int k2s = 2 * k2g + ((cc) >> 2); int cs = (cc) & 3;                                   \
        const float* ap = g_h + ((size_t)(k2s * nmt + mt) * 4 + cs) * 4096;                   \
        const float* bp = g_w2p + (size_t)((k2s * 2 + nh) * 4 + cs) * 2048;                   \
        uint32_t ab = sb + (uint32_t)(st * 4096) * 4;                                         \
        uint32_t bb = sb + (uint32_t)(3 * 4096 + st * 2048) * 4;                              \
        _Pragma("unroll")                                                                      \
        for (int i = 0; i < 4; i++) {                                                          \
            int p = t + i * 256;                                                               \
            cpa16(ab + (uint32_t)p * 16, ap + p * 4);                                          \
        }                                                                                      \
        _Pragma("unroll")                                                                      \
        for (int i = 0; i < 2; i++) {                                                          \
            int p = t + i * 256;                                                               \
            cpa16(bb + (uint32_t)p * 16, bp + p * 4);                                          \
        }                                                                                      \
        CPA_COMMIT();                                                                          \
    } while (0)

    P2_ISSUE(0);
    P2_ISSUE(1);

    int wm = w & 3, wn = w >> 2, g = lane >> 2, tg = lane & 3;
    int m0 = wm * 32;

    float d[2][2][4][4];
#pragma unroll
    for (int kl = 0; kl < 2; kl++)
#pragma unroll
        for (int mi = 0; mi < 2; mi++)
#pragma unroll
            for (int s = 0; s < 4; s++)
#pragma unroll
                for (int j = 0; j < 4; j++) d[kl][mi][s][j] = 0.f;

#pragma unroll
    for (int cc = 0; cc < 8; cc++) {
        if (cc == 7) { CPA_WAIT(0); } else { CPA_WAIT(1); }   // FIX: drain final chunk
        __syncthreads();
        if (cc < 6) P2_ISSUE(cc + 2);
        const float* Ab = sm + (cc % 3) * 4096;
        const float* Bb = sm + 3 * 4096 + (cc % 3) * 2048;
        float (*dk)[4][4] = d[cc >> 2];
#pragma unroll
        for (int kk = 0; kk < 4; kk++) {
            uint32_t a[2][4];
#pragma unroll
            for (int mi = 0; mi < 2; mi++) {
                uint4 av = *(const uint4*)(Ab + (((kk * 8 + wm * 2 + mi) * 8 + g) * 4 + tg) * 4);
                a[mi][0] = av.x; a[mi][1] = av.y; a[mi][2] = av.z; a[mi][3] = av.w;
            }
#pragma unroll
            for (int u = 0; u < 2; u++) {
                uint4 bv = *(const uint4*)(Bb + ((((kk * 2 + u) * 2 + wn) * 8 + g) * 4 + tg) * 4);
                uint32_t blo[2] = {bv.x, bv.y}, bhi[2] = {bv.z, bv.w};
                mma8(dk[0][2 * u], a[0], blo);
                mma8(dk[1][2 * u], a[1], blo);
                mma8(dk[0][2 * u + 1], a[0], bhi);
                mma8(dk[1][2 * u + 1], a[1], bhi);
            }
        }
    }

    // epilogue: float4 at out[row][q*128 + 4*k2g] = {k2l0(q), k2l0(q+64), k2l1(q), k2l1(q+64)} + bias
#pragma unroll
    for (int mi = 0; mi < 2; mi++)
#pragma unroll
        for (int rh = 0; rh < 2; rh++) {
            int row = b0 + m0 + mi * 16 + g + rh * 8;
            if (row < Btok) {
                float* orow = OUT + (size_t)row * SIZE + 4 * k2g;
#pragma unroll
                for (int s2 = 0; s2 < 2; s2++)
#pragma unroll
                    for (int par = 0; par < 2; par++) {
                        int ql = wn * 16 + s2 * 8 + 2 * tg + par;   // 0..31
                        float4 bv = bsh[ql];
                        float4 o;
                        o.x = d[0][mi][s2][rh * 2 + par] + bv.x;
                        o.y = d[0][mi][s2 + 2][rh * 2 + par] + bv.y;
                        o.z = d[1][mi][s2][rh * 2 + par] + bv.z;
                        o.w = d[1][mi][s2 + 2][rh * 2 + par] + bv.w;
                        *(float4*)(orow + (size_t)(q0 + ql) * BS) = o;
                    }
            }
        }
}

// ---------------- launch ----------------
extern "C" void kernel_launch(void* const* d_in, const int* in_sizes, int n_in,
                              void* d_out, int out_size) {
    (void)n_in; (void)out_size;
    const float* x = (const float*)d_in[0];
    const float* w1 = (const float*)d_in[1];
    const float* w2 = (const float*)d_in[2];
    const float* bias = (const float*)d_in[3];
    float* out = (float*)d_out;
    int B = in_sizes[0] / SIZE;
    int mt = (B + 127) / 128;

    cudaFuncSetAttribute(prep_pack, cudaFuncAttributeMaxDynamicSharedMemorySize, SMEMP);
    cudaFuncSetAttribute(monarch_pass1, cudaFuncAttributeMaxDynamicSharedMemorySize, SMEM1);
    cudaFuncSetAttribute(monarch_pass2, cudaFuncAttributeMaxDynamicSharedMemorySize, SMEM2);

    prep_pack<<<192, 256, SMEMP>>>(w1, w2);
    monarch_pass1<<<dim3(NB, mt), 256, SMEM1>>>(x, B, mt);
    monarch_pass2<<<dim3(NB, mt), 256, SMEM2>>>(bias, out, B, mt);
}